// round 15
// baseline (speedup 1.0000x reference)
#include <cuda_runtime.h>
#include <cuda_fp16.h>
#include <math.h>

#define N_NODES   200000
#define N_EDGES   6400000
#define HIDF      128
#define N_GRAPHS  64
#define SCAN_BLK  1024

typedef unsigned long long ull;
typedef unsigned int uint;

// ---------------- scratch (device globals; referenced from device code ONLY) ----
__device__ float  g_degw[N_NODES];                 // sum(ew) per dst
__device__ int    g_cnt[N_NODES];                  // in-degree (rank counter)
__device__ int    g_rank[N_EDGES];                 // edge rank within its dst
__device__ float  g_dinv[N_NODES];                 // rsqrt(deg+1)
__device__ int    g_rowptr[N_NODES + 1];           // CSR row pointers (final)
__device__ int    g_bsum[256];                     // scan block sums
__device__ int    g_boff[256];                     // scan block offsets
__device__ int2   g_edge[N_EDGES];                 // {src, coef bits} sorted by dst
__device__ __half g_Hh[(size_t)N_NODES * HIDF];    // per-layer H (fp16 gather matrix)
__device__ __half g_Bh[(size_t)N_NODES * HIDF];    // ELU(layer-1 out) in fp16
__device__ float  g_sums[N_GRAPHS * HIDF];
__device__ float  g_counts[N_GRAPHS];

__device__ __forceinline__ void red_addf(float* p, float v) {
    asm volatile("red.global.add.f32 [%0], %1;" :: "l"(p), "f"(v) : "memory");
}

// ---------------- zero scratch ----------------
__global__ void zero_meta_kernel(int n) {
    int i = blockIdx.x * blockDim.x + threadIdx.x;
    if (i < n) {
        g_degw[i] = 0.0f;
        g_cnt[i]  = 0;
    }
}

// ---------------- hist: weighted degree + per-edge rank capture -----------------
__device__ __forceinline__ void hist_one(int e, int d, float w) {
    g_rank[e] = atomicAdd(&g_cnt[d], 1);
    red_addf(&g_degw[d], w);
}

__global__ void hist_kernel(const int* __restrict__ dst,
                            const float* __restrict__ ew, int ne) {
    int q = blockIdx.x * blockDim.x + threadIdx.x;
    int e0 = q * 4;
    if (e0 + 3 < ne) {
        int4   d4 = *(const int4*)(dst + e0);
        float4 w4 = *(const float4*)(ew + e0);
        hist_one(e0 + 0, d4.x, w4.x);
        hist_one(e0 + 1, d4.y, w4.y);
        hist_one(e0 + 2, d4.z, w4.z);
        hist_one(e0 + 3, d4.w, w4.w);
    } else {
        for (int e = e0; e < ne; ++e) hist_one(e, dst[e], ew[e]);
    }
}

// ---------------- scan1: exclusive scan of counts; dinv fused ----------------
__global__ void scan1_kernel(int n) {
    __shared__ int wsum[32];
    const int t = threadIdx.x;
    const int w = t >> 5, l = t & 31;
    const int i = blockIdx.x * SCAN_BLK + t;

    int orig = 0;
    if (i < n) {
        orig = g_cnt[i];
        g_dinv[i] = rsqrtf(g_degw[i] + 1.0f);   // + self-loop weight; always > 0
    }
    int v = orig;
#pragma unroll
    for (int o = 1; o < 32; o <<= 1) {
        int u = __shfl_up_sync(0xffffffffu, v, o);
        if (l >= o) v += u;
    }
    if (l == 31) wsum[w] = v;
    __syncthreads();
    if (t < 32) {
        int s = wsum[t];
#pragma unroll
        for (int o = 1; o < 32; o <<= 1) {
            int u = __shfl_up_sync(0xffffffffu, s, o);
            if (t >= o) s += u;
        }
        wsum[t] = s;
    }
    __syncthreads();

    int excl = v - orig + ((w > 0) ? wsum[w - 1] : 0);
    if (i < n) g_rowptr[i] = excl;
    if (t == SCAN_BLK - 1) g_bsum[blockIdx.x] = excl + orig;
}

__global__ void scan2_kernel(int nb) {
    __shared__ int wsum[8];
    const int t = threadIdx.x;             // 256 threads
    const int w = t >> 5, l = t & 31;
    int orig = (t < nb) ? g_bsum[t] : 0;
    int v = orig;
#pragma unroll
    for (int o = 1; o < 32; o <<= 1) {
        int u = __shfl_up_sync(0xffffffffu, v, o);
        if (l >= o) v += u;
    }
    if (l == 31) wsum[w] = v;
    __syncthreads();
    if (t < 8) {
        int s = wsum[t];
#pragma unroll
        for (int o = 1; o < 8; o <<= 1) {
            int u = __shfl_up_sync(0xffu, s, o);
            if (t >= o) s += u;
        }
        wsum[t] = s;
    }
    __syncthreads();
    int excl = v - orig + ((w > 0) ? wsum[w - 1] : 0);
    if (t < nb) g_boff[t] = excl;
}

// finalize rowptr
__global__ void scan3_kernel(int n, int ne) {
    int i = blockIdx.x * blockDim.x + threadIdx.x;
    if (i < n) g_rowptr[i] += g_boff[i >> 10];
    if (i == 0) g_rowptr[n] = ne;
}

// ---------------- scatter into CSR (ATOMIC-FREE: pos = rowptr + rank) -----------
__device__ __forceinline__ void scatter_one(int e, int s, int d, float w) {
    float c = g_dinv[s] * w * g_dinv[d];
    int pos = g_rowptr[d] + g_rank[e];
    g_edge[pos] = make_int2(s, __float_as_int(c));
}

__global__ void scatter_kernel(const int* __restrict__ src, const int* __restrict__ dst,
                               const float* __restrict__ ew, int ne) {
    int q = blockIdx.x * blockDim.x + threadIdx.x;
    int e0 = q * 4;
    if (e0 + 3 < ne) {
        int4   s4 = *(const int4*)(src + e0);
        int4   d4 = *(const int4*)(dst + e0);
        float4 w4 = *(const float4*)(ew + e0);
        scatter_one(e0 + 0, s4.x, d4.x, w4.x);
        scatter_one(e0 + 1, s4.y, d4.y, w4.y);
        scatter_one(e0 + 2, s4.z, d4.z, w4.z);
        scatter_one(e0 + 3, s4.w, d4.w, w4.w);
    } else {
        for (int e = e0; e < ne; ++e) scatter_one(e, src[e], dst[e], ew[e]);
    }
}

// ---------------- tensor-core GEMM: g_Hh = fp16( A @ W ) ----------------
// src_sel=0: A = Xext (fp32, cvt on load). src_sel=1: A = g_Bh (fp16 direct).
// Serial ordering (agg1 completes before GEMM2) makes in-place g_Hh safe.
__global__ void __launch_bounds__(256)
gemm128_tc_kernel(const float* __restrict__ Xext, const float* __restrict__ W,
                  int n, int src_sel) {
    __shared__ __half sWt[128][132];   // transposed W, fp16, padded

    const int t = threadIdx.x;
    const int w = t >> 5, l = t & 31;

    for (int idx = t; idx < 128 * 128; idx += 256) {
        int k = idx >> 7, nn = idx & 127;
        sWt[nn][k] = __float2half(W[idx]);
    }
    __syncthreads();

    const int row_lo = blockIdx.x * 128 + w * 16 + (l >> 2);
    const int row_hi = row_lo + 8;
    const bool ok_lo = row_lo < n;
    const bool ok_hi = row_hi < n;
    const int kq = (l & 3) * 2;

    float d[16][4];
#pragma unroll
    for (int nt = 0; nt < 16; ++nt)
#pragma unroll
        for (int j = 0; j < 4; ++j) d[nt][j] = 0.0f;

    const float*  xlo = Xext + (size_t)row_lo * HIDF;
    const float*  xhi = Xext + (size_t)row_hi * HIDF;
    const __half* blo = g_Bh + (size_t)row_lo * HIDF;
    const __half* bhi = g_Bh + (size_t)row_hi * HIDF;

#pragma unroll
    for (int kt = 0; kt < 8; ++kt) {
        const int k0 = kt * 16 + kq;
        uint a0, a1, a2, a3;
        if (src_sel) {
            a0 = ok_lo ? *(const uint*)(blo + k0)     : 0u;
            a2 = ok_lo ? *(const uint*)(blo + k0 + 8) : 0u;
            a1 = ok_hi ? *(const uint*)(bhi + k0)     : 0u;
            a3 = ok_hi ? *(const uint*)(bhi + k0 + 8) : 0u;
        } else {
            float2 x00 = ok_lo ? *(const float2*)(xlo + k0)     : make_float2(0.f, 0.f);
            float2 x01 = ok_lo ? *(const float2*)(xlo + k0 + 8) : make_float2(0.f, 0.f);
            float2 x10 = ok_hi ? *(const float2*)(xhi + k0)     : make_float2(0.f, 0.f);
            float2 x11 = ok_hi ? *(const float2*)(xhi + k0 + 8) : make_float2(0.f, 0.f);
            __half2 h;
            h = __floats2half2_rn(x00.x, x00.y); a0 = *(uint*)&h;
            h = __floats2half2_rn(x10.x, x10.y); a1 = *(uint*)&h;
            h = __floats2half2_rn(x01.x, x01.y); a2 = *(uint*)&h;
            h = __floats2half2_rn(x11.x, x11.y); a3 = *(uint*)&h;
        }

#pragma unroll
        for (int nt = 0; nt < 16; ++nt) {
            int nn = nt * 8 + (l >> 2);
            uint b0 = *(const uint*)&sWt[nn][kt * 16 + kq];
            uint b1 = *(const uint*)&sWt[nn][kt * 16 + kq + 8];
            asm volatile(
                "mma.sync.aligned.m16n8k16.row.col.f32.f16.f16.f32 "
                "{%0,%1,%2,%3}, {%4,%5,%6,%7}, {%8,%9}, {%0,%1,%2,%3};"
                : "+f"(d[nt][0]), "+f"(d[nt][1]), "+f"(d[nt][2]), "+f"(d[nt][3])
                : "r"(a0), "r"(a1), "r"(a2), "r"(a3), "r"(b0), "r"(b1));
        }
    }

#pragma unroll
    for (int nt = 0; nt < 16; ++nt) {
        int cn = nt * 8 + (l & 3) * 2;
        if (ok_lo) {
            __half2 h = __floats2half2_rn(d[nt][0], d[nt][1]);
            *(uint*)(g_Hh + (size_t)row_lo * HIDF + cn) = *(uint*)&h;
        }
        if (ok_hi) {
            __half2 h = __floats2half2_rn(d[nt][2], d[nt][3]);
            *(uint*)(g_Hh + (size_t)row_hi * HIDF + cn) = *(uint*)&h;
        }
    }
}

// ---------------- shared CSR-agg gather body (unroll-4) ----------------
__device__ __forceinline__ void acc_edge(float4& acc, int2 ed, int l) {
    float c = __int_as_float(ed.y);
    uint2 gu = *(const uint2*)(g_Hh + (size_t)ed.x * HIDF + l * 4);
    float2 g0 = __half22float2(*(__half2*)&gu.x);
    float2 g1 = __half22float2(*(__half2*)&gu.y);
    acc.x += c * g0.x;
    acc.y += c * g0.y;
    acc.z += c * g1.x;
    acc.w += c * g1.y;
}

__device__ __forceinline__ float4 agg_node(int node, int l,
                                           const float* __restrict__ bias) {
    int beg = g_rowptr[node];
    int end = g_rowptr[node + 1];

    float di = g_dinv[node];
    float s = di * di;
    uint2 hu = *(const uint2*)(g_Hh + (size_t)node * HIDF + l * 4);
    float2 h0 = __half22float2(*(__half2*)&hu.x);
    float2 h1 = __half22float2(*(__half2*)&hu.y);
    float4 b = ((const float4*)bias)[l];
    float4 acc = make_float4(s * h0.x + b.x, s * h0.y + b.y,
                             s * h1.x + b.z, s * h1.y + b.w);

    int e = beg;
    for (; e + 4 <= end; e += 4) {
        int2 ed0 = g_edge[e + 0];
        int2 ed1 = g_edge[e + 1];
        int2 ed2 = g_edge[e + 2];
        int2 ed3 = g_edge[e + 3];
        uint2 u0 = *(const uint2*)(g_Hh + (size_t)ed0.x * HIDF + l * 4);
        uint2 u1 = *(const uint2*)(g_Hh + (size_t)ed1.x * HIDF + l * 4);
        uint2 u2 = *(const uint2*)(g_Hh + (size_t)ed2.x * HIDF + l * 4);
        uint2 u3 = *(const uint2*)(g_Hh + (size_t)ed3.x * HIDF + l * 4);
        float2 a0 = __half22float2(*(__half2*)&u0.x), b0 = __half22float2(*(__half2*)&u0.y);
        float c0 = __int_as_float(ed0.y);
        acc.x += c0 * a0.x; acc.y += c0 * a0.y; acc.z += c0 * b0.x; acc.w += c0 * b0.y;
        float2 a1 = __half22float2(*(__half2*)&u1.x), b1 = __half22float2(*(__half2*)&u1.y);
        float c1 = __int_as_float(ed1.y);
        acc.x += c1 * a1.x; acc.y += c1 * a1.y; acc.z += c1 * b1.x; acc.w += c1 * b1.y;
        float2 a2 = __half22float2(*(__half2*)&u2.x), b2 = __half22float2(*(__half2*)&u2.y);
        float c2 = __int_as_float(ed2.y);
        acc.x += c2 * a2.x; acc.y += c2 * a2.y; acc.z += c2 * b2.x; acc.w += c2 * b2.y;
        float2 a3 = __half22float2(*(__half2*)&u3.x), b3 = __half22float2(*(__half2*)&u3.y);
        float c3 = __int_as_float(ed3.y);
        acc.x += c3 * a3.x; acc.y += c3 * a3.y; acc.z += c3 * b3.x; acc.w += c3 * b3.y;
    }
    for (; e < end; ++e) acc_edge(acc, g_edge[e], l);
    return acc;
}

// ---------------- layer-1 agg: ELU fused, fp16 output for GEMM2 -----------------
__global__ void agg1_kernel(const float* __restrict__ bias, int n) {
    int node = (blockIdx.x * blockDim.x + threadIdx.x) >> 5;
    int l = threadIdx.x & 31;
    if (node >= n) return;
    float4 a = agg_node(node, l, bias);
    a.x = (a.x > 0.0f) ? a.x : expm1f(a.x);
    a.y = (a.y > 0.0f) ? a.y : expm1f(a.y);
    a.z = (a.z > 0.0f) ? a.z : expm1f(a.z);
    a.w = (a.w > 0.0f) ? a.w : expm1f(a.w);
    __half2 h0 = __floats2half2_rn(a.x, a.y);
    __half2 h1 = __floats2half2_rn(a.z, a.w);
    *(uint2*)(g_Bh + (size_t)node * HIDF + l * 4) =
        make_uint2(*(uint*)&h0, *(uint*)&h1);
}

// ---------------- layer-2 agg + fused mean-pool accumulation --------------------
__global__ void agg2_pool_kernel(const float* __restrict__ bias,
                                 const int* __restrict__ batch, int n) {
    __shared__ float sAcc[8][HIDF];   // 4KB
    __shared__ int   sg[8];
    int t = threadIdx.x;
    int w = t >> 5, l = t & 31;
    int node = blockIdx.x * 8 + w;

    float4 acc = make_float4(0.f, 0.f, 0.f, 0.f);
    int gid = -1;
    if (node < n) {
        acc = agg_node(node, l, bias);
        gid = batch[node];
    }
    *(float4*)&sAcc[w][l * 4] = acc;
    if (l == 0) sg[w] = gid;
    __syncthreads();

    if (t < HIDF) {
        int cur = -1; float s = 0.0f;
#pragma unroll
        for (int r = 0; r < 8; ++r) {
            int g = sg[r];
            if (g != cur) {
                if (cur >= 0) atomicAdd(&g_sums[cur * HIDF + t], s);
                cur = g; s = 0.0f;
            }
            if (g >= 0) s += sAcc[r][t];
        }
        if (cur >= 0) atomicAdd(&g_sums[cur * HIDF + t], s);
    }
}

// ---------------- pool prep: zero sums/counts + smem-hist counts ----------------
__global__ void pool_prep_kernel(const int* __restrict__ batch, int n) {
    __shared__ int h[N_GRAPHS];
    int t = threadIdx.x;
    int gidx = blockIdx.x * blockDim.x + t;
    if (gidx < N_GRAPHS * HIDF) g_sums[gidx] = 0.0f;
    if (gidx < N_GRAPHS) g_counts[gidx] = 0.0f;
    if (t < N_GRAPHS) h[t] = 0;
    __syncthreads();
    for (int i = gidx; i < n; i += gridDim.x * blockDim.x)
        atomicAdd(&h[batch[i]], 1);
    __syncthreads();
    if (t < N_GRAPHS && h[t] > 0) atomicAdd(&g_counts[t], (float)h[t]);
}

// ---------------- final FC ----------------
__global__ void fc_kernel(const float* __restrict__ Wfc, const float* __restrict__ bfc,
                          float* __restrict__ out) {
    int g = blockIdx.x, t = threadIdx.x;   // 128 threads
    float cnt = g_counts[g];
    cnt = (cnt > 1.0f) ? cnt : 1.0f;
    float v = g_sums[g * HIDF + t] * (1.0f / cnt) * Wfc[t];
#pragma unroll
    for (int o = 16; o; o >>= 1) v += __shfl_down_sync(0xffffffffu, v, o);
    __shared__ float sr[4];
    if ((t & 31) == 0) sr[t >> 5] = v;
    __syncthreads();
    if (t == 0) out[g] = sr[0] + sr[1] + sr[2] + sr[3] + bfc[0];
}

// ---------------- launch (round-12 structure + atomic-free scatter) -------------
extern "C" void kernel_launch(void* const* d_in, const int* in_sizes, int n_in,
                              void* d_out, int out_size) {
    const float* x   = (const float*)d_in[0];
    const int*   ei  = (const int*)  d_in[1];
    const float* ew  = (const float*)d_in[2];
    const int*   bat = (const int*)  d_in[3];
    const float* W1  = (const float*)d_in[4];
    const float* b1  = (const float*)d_in[5];
    const float* W2  = (const float*)d_in[6];
    const float* b2  = (const float*)d_in[7];
    const float* Wfc = (const float*)d_in[8];
    const float* bfc = (const float*)d_in[9];
    float* out = (float*)d_out;

    const int n  = in_sizes[3];   // nodes
    const int ne = in_sizes[2];   // edges
    const int* src = ei;
    const int* dst = ei + ne;

    const int nb = (n + SCAN_BLK - 1) / SCAN_BLK;
    const int gemm_blocks = (n + 127) / 128;
    const int agg_blocks  = (n + 7) / 8;
    const int eq_blocks   = ((ne + 3) / 4 + 255) / 256;

    cudaStream_t s2;
    cudaStreamCreateWithFlags(&s2, cudaStreamNonBlocking);
    cudaEvent_t evF, evJ;
    cudaEventCreateWithFlags(&evF, cudaEventDisableTiming);
    cudaEventCreateWithFlags(&evJ, cudaEventDisableTiming);

    zero_meta_kernel<<<(n + 255) / 256, 256>>>(n);

    // fork: GEMM1 + pool prep, independent of preprocess
    cudaEventRecord(evF, 0);
    cudaStreamWaitEvent(s2, evF, 0);
    gemm128_tc_kernel<<<gemm_blocks, 256, 0, s2>>>(x, W1, n, 0);
    pool_prep_kernel<<<32, 256, 0, s2>>>(bat, n);
    cudaEventRecord(evJ, s2);

    // main: preprocess chain (scatter is atomic-free via g_rank)
    hist_kernel<<<eq_blocks, 256>>>(dst, ew, ne);
    scan1_kernel<<<nb, SCAN_BLK>>>(n);
    scan2_kernel<<<1, 256>>>(nb);
    scan3_kernel<<<(n + 255) / 256, 256>>>(n, ne);
    scatter_kernel<<<eq_blocks, 256>>>(src, dst, ew, ne);

    // join, then the serial tail
    cudaStreamWaitEvent(0, evJ, 0);
    agg1_kernel<<<agg_blocks, 256>>>(b1, n);
    gemm128_tc_kernel<<<gemm_blocks, 256>>>(x /*unused*/, W2, n, 1);
    agg2_pool_kernel<<<agg_blocks, 256>>>(b2, bat, n);
    fc_kernel<<<N_GRAPHS, HIDF>>>(Wfc, bfc, out);
}

// round 16
// speedup vs baseline: 1.0818x; 1.0818x over previous
#include <cuda_runtime.h>
#include <cuda_fp16.h>
#include <math.h>

#define N_NODES   200000
#define N_EDGES   6400000
#define HIDF      128
#define N_GRAPHS  64
#define SCAN_BLK  1024

typedef unsigned long long ull;
typedef unsigned int uint;

// ---------------- scratch (device globals; referenced from device code ONLY) ----
__device__ float2 g_deg2[N_NODES];                 // {sum(ew), edge count} per dst
__device__ float  g_dinv[N_NODES];                 // rsqrt(deg+1)
__device__ int    g_fill[N_NODES];                 // scatter cursor (init = rowptr)
__device__ int    g_rowptr[N_NODES + 1];           // CSR row pointers (final)
__device__ int    g_bsum[256];                     // scan block sums
__device__ int    g_boff[256];                     // scan block offsets
__device__ int2   g_edge[N_EDGES];                 // {src, coef bits} sorted by dst
__device__ __half g_Hh[(size_t)N_NODES * HIDF];    // per-layer H (fp16 gather matrix)
__device__ __half g_Bh[(size_t)N_NODES * HIDF];    // ELU(layer-1 out) in fp16
__device__ float  g_sums[N_GRAPHS * HIDF];
__device__ float  g_counts[N_GRAPHS];

// Blackwell vector reduction: single no-return atomic for {weight, count}
__device__ __forceinline__ void red_add2(float2* p, float a, float b) {
    asm volatile("red.global.add.v2.f32 [%0], {%1, %2};"
                 :: "l"(p), "f"(a), "f"(b) : "memory");
}

// ---------------- zero scratch ----------------
__global__ void zero_meta_kernel(int n) {
    int i = blockIdx.x * blockDim.x + threadIdx.x;
    if (i < n) g_deg2[i] = make_float2(0.0f, 0.0f);
}

// ---------------- hist: weighted degree + count, one vector atomic/edge --------
__global__ void hist_kernel(const int* __restrict__ dst,
                            const float* __restrict__ ew, int ne) {
    int q = blockIdx.x * blockDim.x + threadIdx.x;
    int e0 = q * 4;
    if (e0 + 3 < ne) {
        int4   d4 = *(const int4*)(dst + e0);
        float4 w4 = *(const float4*)(ew + e0);
        red_add2(&g_deg2[d4.x], w4.x, 1.0f);
        red_add2(&g_deg2[d4.y], w4.y, 1.0f);
        red_add2(&g_deg2[d4.z], w4.z, 1.0f);
        red_add2(&g_deg2[d4.w], w4.w, 1.0f);
    } else {
        for (int e = e0; e < ne; ++e) red_add2(&g_deg2[dst[e]], ew[e], 1.0f);
    }
}

// ---------------- scan1: exclusive scan of counts; dinv fused ----------------
__global__ void scan1_kernel(int n) {
    __shared__ int wsum[32];
    const int t = threadIdx.x;
    const int w = t >> 5, l = t & 31;
    const int i = blockIdx.x * SCAN_BLK + t;

    int orig = 0;
    if (i < n) {
        float2 d2 = g_deg2[i];
        orig = __float2int_rn(d2.y);
        g_dinv[i] = rsqrtf(d2.x + 1.0f);   // + self-loop weight; always > 0
    }
    int v = orig;
#pragma unroll
    for (int o = 1; o < 32; o <<= 1) {
        int u = __shfl_up_sync(0xffffffffu, v, o);
        if (l >= o) v += u;
    }
    if (l == 31) wsum[w] = v;
    __syncthreads();
    if (t < 32) {
        int s = wsum[t];
#pragma unroll
        for (int o = 1; o < 32; o <<= 1) {
            int u = __shfl_up_sync(0xffffffffu, s, o);
            if (t >= o) s += u;
        }
        wsum[t] = s;
    }
    __syncthreads();

    int excl = v - orig + ((w > 0) ? wsum[w - 1] : 0);
    if (i < n) g_rowptr[i] = excl;
    if (t == SCAN_BLK - 1) g_bsum[blockIdx.x] = excl + orig;
}

__global__ void scan2_kernel(int nb) {
    __shared__ int wsum[8];
    const int t = threadIdx.x;             // 256 threads
    const int w = t >> 5, l = t & 31;
    int orig = (t < nb) ? g_bsum[t] : 0;
    int v = orig;
#pragma unroll
    for (int o = 1; o < 32; o <<= 1) {
        int u = __shfl_up_sync(0xffffffffu, v, o);
        if (l >= o) v += u;
    }
    if (l == 31) wsum[w] = v;
    __syncthreads();
    if (t < 8) {
        int s = wsum[t];
#pragma unroll
        for (int o = 1; o < 8; o <<= 1) {
            int u = __shfl_up_sync(0xffu, s, o);
            if (t >= o) s += u;
        }
        wsum[t] = s;
    }
    __syncthreads();
    int excl = v - orig + ((w > 0) ? wsum[w - 1] : 0);
    if (t < nb) g_boff[t] = excl;
}

// finalize rowptr + seed scatter cursor with it
__global__ void scan3_kernel(int n, int ne) {
    int i = blockIdx.x * blockDim.x + threadIdx.x;
    if (i < n) {
        int rp = g_rowptr[i] + g_boff[i >> 10];
        g_rowptr[i] = rp;
        g_fill[i] = rp;
    }
    if (i == 0) g_rowptr[n] = ne;
}

// ---------------- scatter into CSR (cursor doubles as position) -----------------
__device__ __forceinline__ void scatter_one(int s, int d, float w) {
    float c = g_dinv[s] * w * g_dinv[d];
    int pos = atomicAdd(&g_fill[d], 1);
    g_edge[pos] = make_int2(s, __float_as_int(c));
}

__global__ void scatter_kernel(const int* __restrict__ src, const int* __restrict__ dst,
                               const float* __restrict__ ew, int ne) {
    int q = blockIdx.x * blockDim.x + threadIdx.x;
    int e0 = q * 4;
    if (e0 + 3 < ne) {
        int4   s4 = *(const int4*)(src + e0);
        int4   d4 = *(const int4*)(dst + e0);
        float4 w4 = *(const float4*)(ew + e0);
        scatter_one(s4.x, d4.x, w4.x);
        scatter_one(s4.y, d4.y, w4.y);
        scatter_one(s4.z, d4.z, w4.z);
        scatter_one(s4.w, d4.w, w4.w);
    } else {
        for (int e = e0; e < ne; ++e) scatter_one(src[e], dst[e], ew[e]);
    }
}

// ---------------- tensor-core GEMM: g_Hh = fp16( A @ W ) ----------------
// src_sel=0: A = Xext (fp32, cvt on load). src_sel=1: A = g_Bh (fp16 direct).
// Serial ordering (agg1 completes before GEMM2) makes in-place g_Hh safe.
__global__ void __launch_bounds__(256)
gemm128_tc_kernel(const float* __restrict__ Xext, const float* __restrict__ W,
                  int n, int src_sel) {
    __shared__ __half sWt[128][132];   // transposed W, fp16, padded

    const int t = threadIdx.x;
    const int w = t >> 5, l = t & 31;

    for (int idx = t; idx < 128 * 128; idx += 256) {
        int k = idx >> 7, nn = idx & 127;
        sWt[nn][k] = __float2half(W[idx]);
    }
    __syncthreads();

    const int row_lo = blockIdx.x * 128 + w * 16 + (l >> 2);
    const int row_hi = row_lo + 8;
    const bool ok_lo = row_lo < n;
    const bool ok_hi = row_hi < n;
    const int kq = (l & 3) * 2;

    float d[16][4];
#pragma unroll
    for (int nt = 0; nt < 16; ++nt)
#pragma unroll
        for (int j = 0; j < 4; ++j) d[nt][j] = 0.0f;

    const float*  xlo = Xext + (size_t)row_lo * HIDF;
    const float*  xhi = Xext + (size_t)row_hi * HIDF;
    const __half* blo = g_Bh + (size_t)row_lo * HIDF;
    const __half* bhi = g_Bh + (size_t)row_hi * HIDF;

#pragma unroll
    for (int kt = 0; kt < 8; ++kt) {
        const int k0 = kt * 16 + kq;
        uint a0, a1, a2, a3;
        if (src_sel) {
            a0 = ok_lo ? *(const uint*)(blo + k0)     : 0u;
            a2 = ok_lo ? *(const uint*)(blo + k0 + 8) : 0u;
            a1 = ok_hi ? *(const uint*)(bhi + k0)     : 0u;
            a3 = ok_hi ? *(const uint*)(bhi + k0 + 8) : 0u;
        } else {
            float2 x00 = ok_lo ? *(const float2*)(xlo + k0)     : make_float2(0.f, 0.f);
            float2 x01 = ok_lo ? *(const float2*)(xlo + k0 + 8) : make_float2(0.f, 0.f);
            float2 x10 = ok_hi ? *(const float2*)(xhi + k0)     : make_float2(0.f, 0.f);
            float2 x11 = ok_hi ? *(const float2*)(xhi + k0 + 8) : make_float2(0.f, 0.f);
            __half2 h;
            h = __floats2half2_rn(x00.x, x00.y); a0 = *(uint*)&h;
            h = __floats2half2_rn(x10.x, x10.y); a1 = *(uint*)&h;
            h = __floats2half2_rn(x01.x, x01.y); a2 = *(uint*)&h;
            h = __floats2half2_rn(x11.x, x11.y); a3 = *(uint*)&h;
        }

#pragma unroll
        for (int nt = 0; nt < 16; ++nt) {
            int nn = nt * 8 + (l >> 2);
            uint b0 = *(const uint*)&sWt[nn][kt * 16 + kq];
            uint b1 = *(const uint*)&sWt[nn][kt * 16 + kq + 8];
            asm volatile(
                "mma.sync.aligned.m16n8k16.row.col.f32.f16.f16.f32 "
                "{%0,%1,%2,%3}, {%4,%5,%6,%7}, {%8,%9}, {%0,%1,%2,%3};"
                : "+f"(d[nt][0]), "+f"(d[nt][1]), "+f"(d[nt][2]), "+f"(d[nt][3])
                : "r"(a0), "r"(a1), "r"(a2), "r"(a3), "r"(b0), "r"(b1));
        }
    }

#pragma unroll
    for (int nt = 0; nt < 16; ++nt) {
        int cn = nt * 8 + (l & 3) * 2;
        if (ok_lo) {
            __half2 h = __floats2half2_rn(d[nt][0], d[nt][1]);
            *(uint*)(g_Hh + (size_t)row_lo * HIDF + cn) = *(uint*)&h;
        }
        if (ok_hi) {
            __half2 h = __floats2half2_rn(d[nt][2], d[nt][3]);
            *(uint*)(g_Hh + (size_t)row_hi * HIDF + cn) = *(uint*)&h;
        }
    }
}

// ---------------- shared CSR-agg gather body (unroll-4) ----------------
__device__ __forceinline__ void acc_edge(float4& acc, int2 ed, int l) {
    float c = __int_as_float(ed.y);
    uint2 gu = *(const uint2*)(g_Hh + (size_t)ed.x * HIDF + l * 4);
    float2 g0 = __half22float2(*(__half2*)&gu.x);
    float2 g1 = __half22float2(*(__half2*)&gu.y);
    acc.x += c * g0.x;
    acc.y += c * g0.y;
    acc.z += c * g1.x;
    acc.w += c * g1.y;
}

__device__ __forceinline__ float4 agg_node(int node, int l,
                                           const float* __restrict__ bias) {
    int beg = g_rowptr[node];
    int end = g_rowptr[node + 1];

    float di = g_dinv[node];
    float s = di * di;
    uint2 hu = *(const uint2*)(g_Hh + (size_t)node * HIDF + l * 4);
    float2 h0 = __half22float2(*(__half2*)&hu.x);
    float2 h1 = __half22float2(*(__half2*)&hu.y);
    float4 b = ((const float4*)bias)[l];
    float4 acc = make_float4(s * h0.x + b.x, s * h0.y + b.y,
                             s * h1.x + b.z, s * h1.y + b.w);

    int e = beg;
    for (; e + 4 <= end; e += 4) {
        int2 ed0 = g_edge[e + 0];
        int2 ed1 = g_edge[e + 1];
        int2 ed2 = g_edge[e + 2];
        int2 ed3 = g_edge[e + 3];
        uint2 u0 = *(const uint2*)(g_Hh + (size_t)ed0.x * HIDF + l * 4);
        uint2 u1 = *(const uint2*)(g_Hh + (size_t)ed1.x * HIDF + l * 4);
        uint2 u2 = *(const uint2*)(g_Hh + (size_t)ed2.x * HIDF + l * 4);
        uint2 u3 = *(const uint2*)(g_Hh + (size_t)ed3.x * HIDF + l * 4);
        float2 a0 = __half22float2(*(__half2*)&u0.x), b0 = __half22float2(*(__half2*)&u0.y);
        float c0 = __int_as_float(ed0.y);
        acc.x += c0 * a0.x; acc.y += c0 * a0.y; acc.z += c0 * b0.x; acc.w += c0 * b0.y;
        float2 a1 = __half22float2(*(__half2*)&u1.x), b1 = __half22float2(*(__half2*)&u1.y);
        float c1 = __int_as_float(ed1.y);
        acc.x += c1 * a1.x; acc.y += c1 * a1.y; acc.z += c1 * b1.x; acc.w += c1 * b1.y;
        float2 a2 = __half22float2(*(__half2*)&u2.x), b2 = __half22float2(*(__half2*)&u2.y);
        float c2 = __int_as_float(ed2.y);
        acc.x += c2 * a2.x; acc.y += c2 * a2.y; acc.z += c2 * b2.x; acc.w += c2 * b2.y;
        float2 a3 = __half22float2(*(__half2*)&u3.x), b3 = __half22float2(*(__half2*)&u3.y);
        float c3 = __int_as_float(ed3.y);
        acc.x += c3 * a3.x; acc.y += c3 * a3.y; acc.z += c3 * b3.x; acc.w += c3 * b3.y;
    }
    for (; e < end; ++e) acc_edge(acc, g_edge[e], l);
    return acc;
}

// ---------------- layer-1 agg: ELU fused, fp16 output for GEMM2 -----------------
__global__ void agg1_kernel(const float* __restrict__ bias, int n) {
    int node = (blockIdx.x * blockDim.x + threadIdx.x) >> 5;
    int l = threadIdx.x & 31;
    if (node >= n) return;
    float4 a = agg_node(node, l, bias);
    a.x = (a.x > 0.0f) ? a.x : expm1f(a.x);
    a.y = (a.y > 0.0f) ? a.y : expm1f(a.y);
    a.z = (a.z > 0.0f) ? a.z : expm1f(a.z);
    a.w = (a.w > 0.0f) ? a.w : expm1f(a.w);
    __half2 h0 = __floats2half2_rn(a.x, a.y);
    __half2 h1 = __floats2half2_rn(a.z, a.w);
    *(uint2*)(g_Bh + (size_t)node * HIDF + l * 4) =
        make_uint2(*(uint*)&h0, *(uint*)&h1);
}

// ---------------- layer-2 agg + fused mean-pool accumulation --------------------
__global__ void agg2_pool_kernel(const float* __restrict__ bias,
                                 const int* __restrict__ batch, int n) {
    __shared__ float sAcc[8][HIDF];   // 4KB
    __shared__ int   sg[8];
    int t = threadIdx.x;
    int w = t >> 5, l = t & 31;
    int node = blockIdx.x * 8 + w;

    float4 acc = make_float4(0.f, 0.f, 0.f, 0.f);
    int gid = -1;
    if (node < n) {
        acc = agg_node(node, l, bias);
        gid = batch[node];
    }
    *(float4*)&sAcc[w][l * 4] = acc;
    if (l == 0) sg[w] = gid;
    __syncthreads();

    if (t < HIDF) {
        int cur = -1; float s = 0.0f;
#pragma unroll
        for (int r = 0; r < 8; ++r) {
            int g = sg[r];
            if (g != cur) {
                if (cur >= 0) atomicAdd(&g_sums[cur * HIDF + t], s);
                cur = g; s = 0.0f;
            }
            if (g >= 0) s += sAcc[r][t];
        }
        if (cur >= 0) atomicAdd(&g_sums[cur * HIDF + t], s);
    }
}

// ---------------- pool prep: zero sums/counts + smem-hist counts ----------------
__global__ void pool_prep_kernel(const int* __restrict__ batch, int n) {
    __shared__ int h[N_GRAPHS];
    int t = threadIdx.x;
    int gidx = blockIdx.x * blockDim.x + t;
    if (gidx < N_GRAPHS * HIDF) g_sums[gidx] = 0.0f;
    if (gidx < N_GRAPHS) g_counts[gidx] = 0.0f;
    if (t < N_GRAPHS) h[t] = 0;
    __syncthreads();
    for (int i = gidx; i < n; i += gridDim.x * blockDim.x)
        atomicAdd(&h[batch[i]], 1);
    __syncthreads();
    if (t < N_GRAPHS && h[t] > 0) atomicAdd(&g_counts[t], (float)h[t]);
}

// ---------------- final FC ----------------
__global__ void fc_kernel(const float* __restrict__ Wfc, const float* __restrict__ bfc,
                          float* __restrict__ out) {
    int g = blockIdx.x, t = threadIdx.x;   // 128 threads
    float cnt = g_counts[g];
    cnt = (cnt > 1.0f) ? cnt : 1.0f;
    float v = g_sums[g * HIDF + t] * (1.0f / cnt) * Wfc[t];
#pragma unroll
    for (int o = 16; o; o >>= 1) v += __shfl_down_sync(0xffffffffu, v, o);
    __shared__ float sr[4];
    if ((t & 31) == 0) sr[t >> 5] = v;
    __syncthreads();
    if (t == 0) out[g] = sr[0] + sr[1] + sr[2] + sr[3] + bfc[0];
}

// ---------------- launch (round-12 champion + merged pool prep) -----------------
extern "C" void kernel_launch(void* const* d_in, const int* in_sizes, int n_in,
                              void* d_out, int out_size) {
    const float* x   = (const float*)d_in[0];
    const int*   ei  = (const int*)  d_in[1];
    const float* ew  = (const float*)d_in[2];
    const int*   bat = (const int*)  d_in[3];
    const float* W1  = (const float*)d_in[4];
    const float* b1  = (const float*)d_in[5];
    const float* W2  = (const float*)d_in[6];
    const float* b2  = (const float*)d_in[7];
    const float* Wfc = (const float*)d_in[8];
    const float* bfc = (const float*)d_in[9];
    float* out = (float*)d_out;

    const int n  = in_sizes[3];   // nodes
    const int ne = in_sizes[2];   // edges
    const int* src = ei;
    const int* dst = ei + ne;

    const int nb = (n + SCAN_BLK - 1) / SCAN_BLK;
    const int gemm_blocks = (n + 127) / 128;
    const int agg_blocks  = (n + 7) / 8;
    const int eq_blocks   = ((ne + 3) / 4 + 255) / 256;

    cudaStream_t s2;
    cudaStreamCreateWithFlags(&s2, cudaStreamNonBlocking);
    cudaEvent_t evF, evJ;
    cudaEventCreateWithFlags(&evF, cudaEventDisableTiming);
    cudaEventCreateWithFlags(&evJ, cudaEventDisableTiming);

    zero_meta_kernel<<<(n + 255) / 256, 256>>>(n);

    // fork: GEMM1 + pool prep, independent of preprocess
    cudaEventRecord(evF, 0);
    cudaStreamWaitEvent(s2, evF, 0);
    gemm128_tc_kernel<<<gemm_blocks, 256, 0, s2>>>(x, W1, n, 0);
    pool_prep_kernel<<<32, 256, 0, s2>>>(bat, n);
    cudaEventRecord(evJ, s2);

    // main: preprocess chain
    hist_kernel<<<eq_blocks, 256>>>(dst, ew, ne);
    scan1_kernel<<<nb, SCAN_BLK>>>(n);
    scan2_kernel<<<1, 256>>>(nb);
    scan3_kernel<<<(n + 255) / 256, 256>>>(n, ne);
    scatter_kernel<<<eq_blocks, 256>>>(src, dst, ew, ne);

    // join, then the serial tail
    cudaStreamWaitEvent(0, evJ, 0);
    agg1_kernel<<<agg_blocks, 256>>>(b1, n);
    gemm128_tc_kernel<<<gemm_blocks, 256>>>(x /*unused*/, W2, n, 1);
    agg2_pool_kernel<<<agg_blocks, 256>>>(b2, bat, n);
    fc_kernel<<<N_GRAPHS, HIDF>>>(Wfc, bfc, out);
}

// round 17
// speedup vs baseline: 1.2350x; 1.1416x over previous
#include <cuda_runtime.h>
#include <cuda_fp16.h>
#include <math.h>

#define N_NODES   200000
#define N_EDGES   6400000
#define HIDF      128
#define N_GRAPHS  64
#define SCAN_BLK  1024

typedef unsigned long long ull;
typedef unsigned int uint;

// ---------------- scratch (device globals; referenced from device code ONLY) ----
__device__ float2 g_deg2[N_NODES];                 // {sum(ew), edge count} per dst
__device__ float  g_dinv[N_NODES];                 // rsqrt(deg+1)
__device__ int    g_fill[N_NODES];                 // scatter cursor (init = rowptr)
__device__ int    g_rowptr[N_NODES + 1];           // CSR row pointers (final)
__device__ int    g_bsum[256];                     // scan block sums
__device__ int    g_boff[256];                     // scan block offsets
__device__ int2   g_edge[N_EDGES];                 // {src, coef bits} sorted by dst
__device__ __half g_Hh[(size_t)N_NODES * HIDF];    // layer-1 H (fp16 gather matrix)
__device__ __half g_Bh[(size_t)N_NODES * HIDF];    // B1' = ELU(layer-1 out), fp16
__device__ float  g_sums[N_GRAPHS * HIDF];         // per-graph Σ of agg2 PRE-GEMM
__device__ float  g_counts[N_GRAPHS];

// Blackwell vector reduction: single no-return atomic for {weight, count}
__device__ __forceinline__ void red_add2(float2* p, float a, float b) {
    asm volatile("red.global.add.v2.f32 [%0], {%1, %2};"
                 :: "l"(p), "f"(a), "f"(b) : "memory");
}

// ---------------- zero scratch ----------------
__global__ void zero_meta_kernel(int n) {
    int i = blockIdx.x * blockDim.x + threadIdx.x;
    if (i < n) g_deg2[i] = make_float2(0.0f, 0.0f);
}

// ---------------- hist: weighted degree + count, one vector atomic/edge --------
__global__ void hist_kernel(const int* __restrict__ dst,
                            const float* __restrict__ ew, int ne) {
    int q = blockIdx.x * blockDim.x + threadIdx.x;
    int e0 = q * 4;
    if (e0 + 3 < ne) {
        int4   d4 = *(const int4*)(dst + e0);
        float4 w4 = *(const float4*)(ew + e0);
        red_add2(&g_deg2[d4.x], w4.x, 1.0f);
        red_add2(&g_deg2[d4.y], w4.y, 1.0f);
        red_add2(&g_deg2[d4.z], w4.z, 1.0f);
        red_add2(&g_deg2[d4.w], w4.w, 1.0f);
    } else {
        for (int e = e0; e < ne; ++e) red_add2(&g_deg2[dst[e]], ew[e], 1.0f);
    }
}

// ---------------- scan1: exclusive scan of counts; dinv fused ----------------
__global__ void scan1_kernel(int n) {
    __shared__ int wsum[32];
    const int t = threadIdx.x;
    const int w = t >> 5, l = t & 31;
    const int i = blockIdx.x * SCAN_BLK + t;

    int orig = 0;
    if (i < n) {
        float2 d2 = g_deg2[i];
        orig = __float2int_rn(d2.y);
        g_dinv[i] = rsqrtf(d2.x + 1.0f);   // + self-loop weight; always > 0
    }
    int v = orig;
#pragma unroll
    for (int o = 1; o < 32; o <<= 1) {
        int u = __shfl_up_sync(0xffffffffu, v, o);
        if (l >= o) v += u;
    }
    if (l == 31) wsum[w] = v;
    __syncthreads();
    if (t < 32) {
        int s = wsum[t];
#pragma unroll
        for (int o = 1; o < 32; o <<= 1) {
            int u = __shfl_up_sync(0xffffffffu, s, o);
            if (t >= o) s += u;
        }
        wsum[t] = s;
    }
    __syncthreads();

    int excl = v - orig + ((w > 0) ? wsum[w - 1] : 0);
    if (i < n) g_rowptr[i] = excl;
    if (t == SCAN_BLK - 1) g_bsum[blockIdx.x] = excl + orig;
}

__global__ void scan2_kernel(int nb) {
    __shared__ int wsum[8];
    const int t = threadIdx.x;             // 256 threads
    const int w = t >> 5, l = t & 31;
    int orig = (t < nb) ? g_bsum[t] : 0;
    int v = orig;
#pragma unroll
    for (int o = 1; o < 32; o <<= 1) {
        int u = __shfl_up_sync(0xffffffffu, v, o);
        if (l >= o) v += u;
    }
    if (l == 31) wsum[w] = v;
    __syncthreads();
    if (t < 8) {
        int s = wsum[t];
#pragma unroll
        for (int o = 1; o < 8; o <<= 1) {
            int u = __shfl_up_sync(0xffu, s, o);
            if (t >= o) s += u;
        }
        wsum[t] = s;
    }
    __syncthreads();
    int excl = v - orig + ((w > 0) ? wsum[w - 1] : 0);
    if (t < nb) g_boff[t] = excl;
}

// finalize rowptr + seed scatter cursor with it
__global__ void scan3_kernel(int n, int ne) {
    int i = blockIdx.x * blockDim.x + threadIdx.x;
    if (i < n) {
        int rp = g_rowptr[i] + g_boff[i >> 10];
        g_rowptr[i] = rp;
        g_fill[i] = rp;
    }
    if (i == 0) g_rowptr[n] = ne;
}

// ---------------- scatter into CSR (cursor doubles as position) -----------------
__device__ __forceinline__ void scatter_one(int s, int d, float w) {
    float c = g_dinv[s] * w * g_dinv[d];
    int pos = atomicAdd(&g_fill[d], 1);
    g_edge[pos] = make_int2(s, __float_as_int(c));
}

__global__ void scatter_kernel(const int* __restrict__ src, const int* __restrict__ dst,
                               const float* __restrict__ ew, int ne) {
    int q = blockIdx.x * blockDim.x + threadIdx.x;
    int e0 = q * 4;
    if (e0 + 3 < ne) {
        int4   s4 = *(const int4*)(src + e0);
        int4   d4 = *(const int4*)(dst + e0);
        float4 w4 = *(const float4*)(ew + e0);
        scatter_one(s4.x, d4.x, w4.x);
        scatter_one(s4.y, d4.y, w4.y);
        scatter_one(s4.z, d4.z, w4.z);
        scatter_one(s4.w, d4.w, w4.w);
    } else {
        for (int e = e0; e < ne; ++e) scatter_one(src[e], dst[e], ew[e]);
    }
}

// ---------------- tensor-core GEMM (layer 1 only): g_Hh = fp16( X @ W1 ) --------
__global__ void __launch_bounds__(256)
gemm128_tc_kernel(const float* __restrict__ Xext, const float* __restrict__ W, int n) {
    __shared__ __half sWt[128][132];   // transposed W, fp16, padded

    const int t = threadIdx.x;
    const int w = t >> 5, l = t & 31;

    for (int idx = t; idx < 128 * 128; idx += 256) {
        int k = idx >> 7, nn = idx & 127;
        sWt[nn][k] = __float2half(W[idx]);
    }
    __syncthreads();

    const int row_lo = blockIdx.x * 128 + w * 16 + (l >> 2);
    const int row_hi = row_lo + 8;
    const bool ok_lo = row_lo < n;
    const bool ok_hi = row_hi < n;
    const int kq = (l & 3) * 2;

    float d[16][4];
#pragma unroll
    for (int nt = 0; nt < 16; ++nt)
#pragma unroll
        for (int j = 0; j < 4; ++j) d[nt][j] = 0.0f;

    const float* xlo = Xext + (size_t)row_lo * HIDF;
    const float* xhi = Xext + (size_t)row_hi * HIDF;

#pragma unroll
    for (int kt = 0; kt < 8; ++kt) {
        const int k0 = kt * 16 + kq;
        float2 x00 = ok_lo ? *(const float2*)(xlo + k0)     : make_float2(0.f, 0.f);
        float2 x01 = ok_lo ? *(const float2*)(xlo + k0 + 8) : make_float2(0.f, 0.f);
        float2 x10 = ok_hi ? *(const float2*)(xhi + k0)     : make_float2(0.f, 0.f);
        float2 x11 = ok_hi ? *(const float2*)(xhi + k0 + 8) : make_float2(0.f, 0.f);
        __half2 h;
        uint a0, a1, a2, a3;
        h = __floats2half2_rn(x00.x, x00.y); a0 = *(uint*)&h;
        h = __floats2half2_rn(x10.x, x10.y); a1 = *(uint*)&h;
        h = __floats2half2_rn(x01.x, x01.y); a2 = *(uint*)&h;
        h = __floats2half2_rn(x11.x, x11.y); a3 = *(uint*)&h;

#pragma unroll
        for (int nt = 0; nt < 16; ++nt) {
            int nn = nt * 8 + (l >> 2);
            uint b0 = *(const uint*)&sWt[nn][kt * 16 + kq];
            uint b1 = *(const uint*)&sWt[nn][kt * 16 + kq + 8];
            asm volatile(
                "mma.sync.aligned.m16n8k16.row.col.f32.f16.f16.f32 "
                "{%0,%1,%2,%3}, {%4,%5,%6,%7}, {%8,%9}, {%0,%1,%2,%3};"
                : "+f"(d[nt][0]), "+f"(d[nt][1]), "+f"(d[nt][2]), "+f"(d[nt][3])
                : "r"(a0), "r"(a1), "r"(a2), "r"(a3), "r"(b0), "r"(b1));
        }
    }

#pragma unroll
    for (int nt = 0; nt < 16; ++nt) {
        int cn = nt * 8 + (l & 3) * 2;
        if (ok_lo) {
            __half2 h = __floats2half2_rn(d[nt][0], d[nt][1]);
            *(uint*)(g_Hh + (size_t)row_lo * HIDF + cn) = *(uint*)&h;
        }
        if (ok_hi) {
            __half2 h = __floats2half2_rn(d[nt][2], d[nt][3]);
            *(uint*)(g_Hh + (size_t)row_hi * HIDF + cn) = *(uint*)&h;
        }
    }
}

// ---------------- shared CSR-agg gather body (unroll-4), param gather matrix ----
__device__ __forceinline__ float4 agg_node(const __half* __restrict__ H,
                                           int node, int l,
                                           const float* __restrict__ bias) {
    int beg = g_rowptr[node];
    int end = g_rowptr[node + 1];

    float di = g_dinv[node];
    float s = di * di;
    uint2 hu = *(const uint2*)(H + (size_t)node * HIDF + l * 4);
    float2 h0 = __half22float2(*(__half2*)&hu.x);
    float2 h1 = __half22float2(*(__half2*)&hu.y);
    float4 b = ((const float4*)bias)[l];
    float4 acc = make_float4(s * h0.x + b.x, s * h0.y + b.y,
                             s * h1.x + b.z, s * h1.y + b.w);

    int e = beg;
    for (; e + 4 <= end; e += 4) {
        int2 ed0 = g_edge[e + 0];
        int2 ed1 = g_edge[e + 1];
        int2 ed2 = g_edge[e + 2];
        int2 ed3 = g_edge[e + 3];
        uint2 u0 = *(const uint2*)(H + (size_t)ed0.x * HIDF + l * 4);
        uint2 u1 = *(const uint2*)(H + (size_t)ed1.x * HIDF + l * 4);
        uint2 u2 = *(const uint2*)(H + (size_t)ed2.x * HIDF + l * 4);
        uint2 u3 = *(const uint2*)(H + (size_t)ed3.x * HIDF + l * 4);
        float2 a0 = __half22float2(*(__half2*)&u0.x), b0 = __half22float2(*(__half2*)&u0.y);
        float c0 = __int_as_float(ed0.y);
        acc.x += c0 * a0.x; acc.y += c0 * a0.y; acc.z += c0 * b0.x; acc.w += c0 * b0.y;
        float2 a1 = __half22float2(*(__half2*)&u1.x), b1 = __half22float2(*(__half2*)&u1.y);
        float c1 = __int_as_float(ed1.y);
        acc.x += c1 * a1.x; acc.y += c1 * a1.y; acc.z += c1 * b1.x; acc.w += c1 * b1.y;
        float2 a2 = __half22float2(*(__half2*)&u2.x), b2 = __half22float2(*(__half2*)&u2.y);
        float c2 = __int_as_float(ed2.y);
        acc.x += c2 * a2.x; acc.y += c2 * a2.y; acc.z += c2 * b2.x; acc.w += c2 * b2.y;
        float2 a3 = __half22float2(*(__half2*)&u3.x), b3 = __half22float2(*(__half2*)&u3.y);
        float c3 = __int_as_float(ed3.y);
        acc.x += c3 * a3.x; acc.y += c3 * a3.y; acc.z += c3 * b3.x; acc.w += c3 * b3.y;
    }
    for (; e < end; ++e) {
        int2 ed = g_edge[e];
        float c = __int_as_float(ed.y);
        uint2 gu = *(const uint2*)(H + (size_t)ed.x * HIDF + l * 4);
        float2 g0 = __half22float2(*(__half2*)&gu.x);
        float2 g1 = __half22float2(*(__half2*)&gu.y);
        acc.x += c * g0.x;
        acc.y += c * g0.y;
        acc.z += c * g1.x;
        acc.w += c * g1.y;
    }
    return acc;
}

// ---------------- layer-1 agg: ELU fused, fp16 output g_Bh ----------------------
__global__ void agg1_kernel(const float* __restrict__ bias, int n) {
    int node = (blockIdx.x * blockDim.x + threadIdx.x) >> 5;
    int l = threadIdx.x & 31;
    if (node >= n) return;
    float4 a = agg_node(g_Hh, node, l, bias);
    a.x = (a.x > 0.0f) ? a.x : expm1f(a.x);
    a.y = (a.y > 0.0f) ? a.y : expm1f(a.y);
    a.z = (a.z > 0.0f) ? a.z : expm1f(a.z);
    a.w = (a.w > 0.0f) ? a.w : expm1f(a.w);
    __half2 h0 = __floats2half2_rn(a.x, a.y);
    __half2 h1 = __floats2half2_rn(a.z, a.w);
    *(uint2*)(g_Bh + (size_t)node * HIDF + l * 4) =
        make_uint2(*(uint*)&h0, *(uint*)&h1);
}

// ---------------- layer-2 agg on B1' (PRE-GEMM) + fused mean-pool ---------------
// By linearity:  Σ_g [norm-sum of (B1'@W2)]  =  (Σ_g [norm-sum of B1']) @ W2.
// So gather g_Bh here; @W2 + b2 happens in the 64-row epilogue (fc2). The bias
// passed here is ZERO (b2 is applied post-GEMM in fc2).
__global__ void agg2_pool_kernel(const float* __restrict__ zero_bias,
                                 const int* __restrict__ batch, int n) {
    __shared__ float sAcc[8][HIDF];   // 4KB
    __shared__ int   sg[8];
    int t = threadIdx.x;
    int w = t >> 5, l = t & 31;
    int node = blockIdx.x * 8 + w;

    float4 acc = make_float4(0.f, 0.f, 0.f, 0.f);
    int gid = -1;
    if (node < n) {
        acc = agg_node(g_Bh, node, l, zero_bias);
        gid = batch[node];
    }
    *(float4*)&sAcc[w][l * 4] = acc;
    if (l == 0) sg[w] = gid;
    __syncthreads();

    if (t < HIDF) {
        int cur = -1; float s = 0.0f;
#pragma unroll
        for (int r = 0; r < 8; ++r) {
            int g = sg[r];
            if (g != cur) {
                if (cur >= 0) atomicAdd(&g_sums[cur * HIDF + t], s);
                cur = g; s = 0.0f;
            }
            if (g >= 0) s += sAcc[r][t];
        }
        if (cur >= 0) atomicAdd(&g_sums[cur * HIDF + t], s);
    }
}

// ---------------- pool prep: zero sums/counts/zero-bias + smem-hist counts ------
__device__ float g_zero_bias[HIDF];

__global__ void pool_prep_kernel(const int* __restrict__ batch, int n) {
    __shared__ int h[N_GRAPHS];
    int t = threadIdx.x;
    int gidx = blockIdx.x * blockDim.x + t;
    if (gidx < N_GRAPHS * HIDF) g_sums[gidx] = 0.0f;
    if (gidx < N_GRAPHS) g_counts[gidx] = 0.0f;
    if (gidx < HIDF) g_zero_bias[gidx] = 0.0f;
    if (t < N_GRAPHS) h[t] = 0;
    __syncthreads();
    for (int i = gidx; i < n; i += gridDim.x * blockDim.x)
        atomicAdd(&h[batch[i]], 1);
    __syncthreads();
    if (t < N_GRAPHS && h[t] > 0) atomicAdd(&g_counts[t], (float)h[t]);
}

// ---------------- fc2: (sums/cnt) @ W2 + b2, then dot Wfc + bfc ----------------
__global__ void fc2_kernel(const float* __restrict__ W2, const float* __restrict__ b2,
                           const float* __restrict__ Wfc, const float* __restrict__ bfc,
                           float* __restrict__ out) {
    __shared__ float sp[HIDF];
    __shared__ float sr[4];
    int g = blockIdx.x, t = threadIdx.x;   // 128 threads

    float cnt = g_counts[g];
    cnt = (cnt > 1.0f) ? cnt : 1.0f;
    float inv = 1.0f / cnt;
    sp[t] = g_sums[g * HIDF + t] * inv;    // mean-pooled pre-GEMM vector
    __syncthreads();

    // h2[t] = sp . W2[:,t] + b2[t]   (coalesced: warp reads W2[k][0..127])
    float acc = b2[t];
#pragma unroll 8
    for (int k = 0; k < HIDF; ++k)
        acc += sp[k] * W2[k * HIDF + t];

    float v = acc * Wfc[t];
#pragma unroll
    for (int o = 16; o; o >>= 1) v += __shfl_down_sync(0xffffffffu, v, o);
    if ((t & 31) == 0) sr[t >> 5] = v;
    __syncthreads();
    if (t == 0) out[g] = sr[0] + sr[1] + sr[2] + sr[3] + bfc[0];
}

// ---------------- launch (champion structure; GEMM2 eliminated) -----------------
extern "C" void kernel_launch(void* const* d_in, const int* in_sizes, int n_in,
                              void* d_out, int out_size) {
    const float* x   = (const float*)d_in[0];
    const int*   ei  = (const int*)  d_in[1];
    const float* ew  = (const float*)d_in[2];
    const int*   bat = (const int*)  d_in[3];
    const float* W1  = (const float*)d_in[4];
    const float* b1  = (const float*)d_in[5];
    const float* W2  = (const float*)d_in[6];
    const float* b2  = (const float*)d_in[7];
    const float* Wfc = (const float*)d_in[8];
    const float* bfc = (const float*)d_in[9];
    float* out = (float*)d_out;

    const int n  = in_sizes[3];   // nodes
    const int ne = in_sizes[2];   // edges
    const int* src = ei;
    const int* dst = ei + ne;

    const int nb = (n + SCAN_BLK - 1) / SCAN_BLK;
    const int gemm_blocks = (n + 127) / 128;
    const int agg_blocks  = (n + 7) / 8;
    const int eq_blocks   = ((ne + 3) / 4 + 255) / 256;

    cudaStream_t s2;
    cudaStreamCreateWithFlags(&s2, cudaStreamNonBlocking);
    cudaEvent_t evF, evJ;
    cudaEventCreateWithFlags(&evF, cudaEventDisableTiming);
    cudaEventCreateWithFlags(&evJ, cudaEventDisableTiming);

    zero_meta_kernel<<<(n + 255) / 256, 256>>>(n);

    // fork: GEMM1 + pool prep, independent of preprocess
    cudaEventRecord(evF, 0);
    cudaStreamWaitEvent(s2, evF, 0);
    gemm128_tc_kernel<<<gemm_blocks, 256, 0, s2>>>(x, W1, n);
    pool_prep_kernel<<<32, 256, 0, s2>>>(bat, n);
    cudaEventRecord(evJ, s2);

    // main: preprocess chain
    hist_kernel<<<eq_blocks, 256>>>(dst, ew, ne);
    scan1_kernel<<<nb, SCAN_BLK>>>(n);
    scan2_kernel<<<1, 256>>>(nb);
    scan3_kernel<<<(n + 255) / 256, 256>>>(n, ne);
    scatter_kernel<<<eq_blocks, 256>>>(src, dst, ew, ne);

    // join, then the serial tail (NO GEMM2 — folded into fc2 by linearity)
    cudaStreamWaitEvent(0, evJ, 0);
    agg1_kernel<<<agg_blocks, 256>>>(b1, n);
    {
        // device address of the zero-bias vector for agg2 (initialized by pool_prep)
        void* p_zb = nullptr;
        cudaGetSymbolAddress(&p_zb, g_zero_bias);
        agg2_pool_kernel<<<agg_blocks, 256>>>((const float*)p_zb, bat, n);
    }
    fc2_kernel<<<N_GRAPHS, HIDF>>>(W2, b2, Wfc, bfc, out);
}